// round 9
// baseline (speedup 1.0000x reference)
#include <cuda_runtime.h>

// EuclideanLoss: loss = mean_n [ w_n * mean_b ||x[b,n,:] - y[b,:,n]||_2 ]
//   x: [B=32, N=8192, D=64] f32   (d_in[0])
//   y: [B=32, D=64, N=8192] f32   (d_in[1])
//   w_n = 1.5 for n in {1,2}, else 1.0
//
// R7: the binder (R3/R5/R6 invariant) is the L1tex wavefront queue: x read
// directly per-row is LDG.128 with 256B lane stride = 32 lines/instr = 512
// wavefronts per 8KB warp-tile (L1 ~56% == dur share). Fix: WARP-private smem
// transpose. Each warp loads its 32 rows coalesced (16 LDG.128/lane, 32
// consecutive float4 per instr = 4 wf) into an 8KB swizzled smem slice, then
// consumes per-row from smem. Only __syncwarp (R4 showed __syncthreads
// phasing kills latency hiding; warp phases stay independent here).
// x wavefronts drop 8x; y unchanged (perfectly coalesced).

#define B_DIM 32
#define N_DIM 8192
#define D_DIM 64
#define THREADS 128                         // 4 warps
#define NBLK ((B_DIM * N_DIM) / THREADS)    // 2048 blocks

__device__ float g_partials[NBLK];
__device__ unsigned int g_count = 0;        // re-armed by the finishing block

__global__ __launch_bounds__(THREADS)
void euclid_fused_kernel(const float* __restrict__ x, const float* __restrict__ y,
                         float* __restrict__ out) {
    // per-warp 8KB slice: 32 rows x 16 float4, XOR-rotate swizzled
    __shared__ float4 sx[4][32 * 16];

    const int tid  = threadIdx.x;
    const int w    = tid >> 5;
    const int lane = tid & 31;
    const int t = blockIdx.x * THREADS + tid;   // this thread's row, 0..B*N-1
    const int b = t >> 13;                      // t / N_DIM
    const int n = t & (N_DIM - 1);              // t % N_DIM

    // ---- coalesced load of this warp's 32 rows (8KB) into smem ----
    // linear float4 index l = i*32+lane over the warp's 512 float4s:
    // each LDG.128 covers 32 consecutive float4 = 512B = 4 lines = 4 wf.
    const float4* __restrict__ xw = reinterpret_cast<const float4*>(x)
        + ((size_t)blockIdx.x * THREADS + 32 * w) * (D_DIM / 4);
#pragma unroll
    for (int i = 0; i < 16; ++i) {
        int l = i * 32 + lane;
        int r = l >> 4;          // row within warp-tile
        int j = l & 15;          // float4 col
        sx[w][r * 16 + ((j + r) & 15)] = xw[l];   // swizzle: bank-conflict-free
    }
    __syncwarp();

    // ---- consume: row 'lane' from smem, y column direct (coalesced) ----
    const float* __restrict__ yp = y + (size_t)b * D_DIM * N_DIM + n;

    float acc0 = 0.0f, acc1 = 0.0f;
#pragma unroll
    for (int j = 0; j < 16; ++j) {
        float4 xv = sx[w][lane * 16 + ((j + lane) & 15)];  // logical col j of row lane
        const float* yq = yp + (size_t)(4 * j) * N_DIM;
        float y0 = yq[0];
        float y1 = yq[(size_t)N_DIM];
        float y2 = yq[(size_t)2 * N_DIM];
        float y3 = yq[(size_t)3 * N_DIM];
        float d;
        d = xv.x - y0; acc0 = fmaf(d, d, acc0);
        d = xv.y - y1; acc1 = fmaf(d, d, acc1);
        d = xv.z - y2; acc0 = fmaf(d, d, acc0);
        d = xv.w - y3; acc1 = fmaf(d, d, acc1);
    }

    float v = sqrtf(acc0 + acc1);
    if ((unsigned)(n - 1) < 2u) v *= 1.5f;      // n == 1 || n == 2

    // ---- deterministic block reduction (4 warps) ----
#pragma unroll
    for (int off = 16; off > 0; off >>= 1)
        v += __shfl_down_sync(0xffffffffu, v, off);

    __shared__ float s_warp[THREADS / 32];
    __shared__ bool s_is_last;
    if (lane == 0) s_warp[w] = v;
    __syncthreads();

    if (tid == 0) {
        v = s_warp[0] + s_warp[1] + s_warp[2] + s_warp[3];
        g_partials[blockIdx.x] = v;
        __threadfence();                        // make partial visible
        unsigned int prev = atomicAdd(&g_count, 1u);
        s_is_last = (prev == NBLK - 1);
    }
    __syncthreads();

    if (!s_is_last) return;

    // ---- finishing block: reduce 2048 partials in FIXED order (bit-stable) ----
    __threadfence();
    float s = 0.0f;
#pragma unroll
    for (int k = 0; k < NBLK / THREADS; ++k)    // 16 partials per thread, fixed order
        s += g_partials[tid + k * THREADS];

#pragma unroll
    for (int off = 16; off > 0; off >>= 1)
        s += __shfl_down_sync(0xffffffffu, s, off);

    if (lane == 0) s_warp[w] = s;
    __syncthreads();

    if (tid == 0) {
        s = s_warp[0] + s_warp[1] + s_warp[2] + s_warp[3];
        out[0] = s * (1.0f / ((float)B_DIM * (float)N_DIM));
        g_count = 0;   // re-arm for the next graph replay
    }
}

extern "C" void kernel_launch(void* const* d_in, const int* in_sizes, int n_in,
                              void* d_out, int out_size) {
    const float* x = (const float*)d_in[0];
    const float* y = (const float*)d_in[1];
    float* out = (float*)d_out;

    euclid_fused_kernel<<<NBLK, THREADS>>>(x, y, out);
}